// round 8
// baseline (speedup 1.0000x reference)
#include <cuda_runtime.h>
#include <cstdint>

// Problem constants: B=128, T=2048, D=256, LAMDA=0.5
#define B_ 128
#define T_ 2048
#define D_ 256
#define S_ 32                          // T-splits (chunks) per (b, tensor)
#define ROWS_ITEM (T_ / S_)            // 64 rows per chunk
#define TILE_ROWS 16
#define TILE_FLOATS (TILE_ROWS * D_)   // 4096
#define TILE_BYTES (TILE_FLOATS * 4)   // 16 KB
#define TPI 4                          // tiles per chunk
#define NSTAGE 3
#define NW 8
#define NTHREADS 256
#define GRID_MAIN 444                  // 148 SMs x 3 CTAs, persistent single wave
#define CPT (GRID_MAIN / 2)            // 222 CTAs per tensor type
#define NIT (B_ * S_)                  // 4096 chunks per tensor
#define NWARPS_TOT (GRID_MAIN * NW)    // 3552 warps chip-wide
#define NDOTS (B_ * D_)                // 32768 mids row-dots

// Dynamic smem layout (bytes) — measured-good R3 streaming config
#define SM_DATA 0
#define SM_RED  (NSTAGE * TILE_BYTES)          // 49152
#define SM_LRED (SM_RED + NW * D_ * 4)         // 57344
#define SM_MBAR (SM_LRED + NW * 4)             // 57376 (8B aligned)
#define SMEM_TOTAL (SM_MBAR + 2 * NSTAGE * 8)  // 57424

// Globals (zero-initialized at module load; counters are monotonic and
// replay-safe via modular logic — never reset).
__device__ float g_mids[B_ * D_];
__device__ float g_pa[NIT][258];   // aspect stream partials (acc[256], L at [256])
__device__ float g_p1[NIT][258];   // sentiment-sentiment stream
__device__ float g_p2[NIT][258];   // sentiment-aspect stream
__device__ unsigned g_bar;         // global barrier counter (+GRID_MAIN per launch)
__device__ unsigned g_cnt_s[B_];   // sentiment chunk-completion counters (+32/launch)
__device__ unsigned g_cnt_a[B_];   // aspect chunk-completion counters   (+32/launch)

__device__ __forceinline__ float warp_sum(float v) {
#pragma unroll
    for (int o = 16; o > 0; o >>= 1) v += __shfl_xor_sync(0xffffffffu, v, o);
    return v;
}
__device__ __forceinline__ uint32_t smem_u32(const void* p) {
    uint32_t a;
    asm("{ .reg .u64 t; cvta.to.shared.u64 t, %1; cvt.u32.u64 %0, t; }"
        : "=r"(a) : "l"(p));
    return a;
}
__device__ __forceinline__ void mbar_init(uint32_t a, uint32_t c) {
    asm volatile("mbarrier.init.shared.b64 [%0], %1;" :: "r"(a), "r"(c) : "memory");
}
__device__ __forceinline__ void mbar_expect_tx(uint32_t a, uint32_t n) {
    asm volatile("mbarrier.arrive.expect_tx.shared.b64 _, [%0], %1;" :: "r"(a), "r"(n) : "memory");
}
__device__ __forceinline__ void mbar_arrive(uint32_t a) {
    asm volatile("mbarrier.arrive.shared.b64 _, [%0];" :: "r"(a) : "memory");
}
__device__ __forceinline__ void mbar_wait(uint32_t a, uint32_t parity) {
    asm volatile(
        "{\n\t.reg .pred P;\n"
        "WL_%=:\n\t"
        "mbarrier.try_wait.parity.acquire.cta.shared::cta.b64 P, [%0], %1, 0x989680;\n\t"
        "@P bra.uni WD_%=;\n\t"
        "bra.uni WL_%=;\n"
        "WD_%=:\n\t}"
        :: "r"(a), "r"(parity) : "memory");
}
__device__ __forceinline__ void bulk_g2s(uint32_t dst, const void* src,
                                         uint32_t bytes, uint32_t mbar) {
    asm volatile(
        "cp.async.bulk.shared::cta.global.mbarrier::complete_tx::bytes [%0], [%1], %2, [%3];"
        :: "r"(dst), "l"(src), "r"(bytes), "r"(mbar) : "memory");
}
__device__ __forceinline__ void fence_async_sc() {
    asm volatile("fence.proxy.async.shared::cta;" ::: "memory");
}
__device__ __forceinline__ float dot8(float4 a, float4 b, float4 c, float4 d) {
    return a.x*b.x + a.y*b.y + a.z*b.z + a.w*b.w
         + c.x*d.x + c.y*d.y + c.z*d.z + c.w*d.w;
}

// ---------------------------------------------------------------------------
// k_main: ONE persistent kernel, grid = 444 (single wave, 3 CTAs/SM).
// Phase 0: every CTA issues its TMA prologue (streaming starts immediately).
// Phase 1: all 3552 warps cooperatively compute mids = W_mul @ aspect[b]
//          (overlapped with the in-flight prologue), then a replay-safe
//          global barrier.
// Phase 2: even CTAs stream aspect_memory (tanh-score softmax), odd CTAs
//          stream sentiment_memory (two softmax streams). 3-stage
//          cp.async.bulk pipeline, full/empty mbarriers. The 32nd CTA to
//          finish a b's chunks performs that b's final combine inline.
// No online max needed: aspect scores = tanh in [-1,1]; sentiment scores are
// O(1) -> plain exp() is safe and equals the reference's shifted softmax.
// Query-side additive terms are constant over t and cancel in the softmax.
// ---------------------------------------------------------------------------
__global__ void __launch_bounds__(NTHREADS, 3) k_main(
    const float* __restrict__ aspect,            // [B,D]
    const float* __restrict__ sentiment_memory,  // [B,T,D]
    const float* __restrict__ aspect_memory,     // [B,T,D]
    const float* __restrict__ mask,              // [B,T]
    const float* __restrict__ W_mul,             // [D,D]
    const float* __restrict__ b_mul,             // [1]
    const float* __restrict__ w_ss,              // [2D] (only [:D] matters)
    const float* __restrict__ w_sa,              // [2D]
    float* __restrict__ out)                     // [2*B*D]
{
    extern __shared__ __align__(1024) unsigned char dynsmem[];
    float* s_data = (float*)(dynsmem + SM_DATA);
    float* s_red  = (float*)(dynsmem + SM_RED);
    float* s_lred = (float*)(dynsmem + SM_LRED);
    const uint32_t mb_full  = smem_u32(dynsmem + SM_MBAR);
    const uint32_t mb_empty = mb_full + NSTAGE * 8;
    const uint32_t sdata    = smem_u32(s_data);
    __shared__ int s_doc;   // combine-election broadcast

    const int cta   = blockIdx.x;
    const int ctype = cta & 1;          // 0 = aspect, 1 = sentiment
    const int tcta  = cta >> 1;
    const int tid   = threadIdx.x;
    const int w     = tid >> 5, lane = tid & 31;

    const int nit   = (NIT - tcta + CPT - 1) / CPT;
    const int ntile = nit * TPI;
    const float* membase = ctype ? sentiment_memory : aspect_memory;

    if (tid == 0) {
#pragma unroll
        for (int i = 0; i < NSTAGE; i++) {
            mbar_init(mb_full + i * 8, 1);
            mbar_init(mb_empty + i * 8, NTHREADS);
        }
        fence_async_sc();
    }
    __syncthreads();

    // ---- Phase 0: TMA prologue (streaming starts now) ----
    int pj = 0, pt = 0;
    const float* pbase = membase
        + ((size_t)(tcta >> 5) * T_ + (size_t)(tcta & 31) * ROWS_ITEM) * D_;
    if (tid == 0) {
#pragma unroll
        for (int i = 0; i < NSTAGE; i++) {   // ntile >= 72 always
            mbar_expect_tx(mb_full + i * 8, TILE_BYTES);
            bulk_g2s(sdata + i * TILE_BYTES, pbase + (size_t)pt * TILE_FLOATS,
                     TILE_BYTES, mb_full + i * 8);
            if (++pt == TPI) {
                pt = 0; pj++;
                if (pj < nit) {
                    const int e2 = tcta + CPT * pj;
                    pbase = membase + ((size_t)(e2 >> 5) * T_
                                     + (size_t)(e2 & 31) * ROWS_ITEM) * D_;
                }
            }
        }
    }

    // ---- Phase 1: cooperative mids GEMV (overlaps prologue DRAM traffic) ----
    {
        const int gid = cta * NW + w;
        for (int idx = gid; idx < NDOTS; idx += NWARPS_TOT) {
            const int b   = idx >> 8;
            const int row = idx & (D_ - 1);
            const float4* Wr = (const float4*)(W_mul + (size_t)row * D_);
            const float4* Ar = (const float4*)(aspect + (size_t)b * D_);
            float p = dot8(Wr[lane], Ar[lane], Wr[32 + lane], Ar[32 + lane]);
            p = warp_sum(p);
            if (lane == 0) g_mids[b * D_ + row] = p;
        }
    }
    __syncthreads();
    // Replay-safe global barrier: counter is monotonic; each launch adds
    // exactly GRID_MAIN, and stream-ordering separates launches.
    if (tid == 0) {
        __threadfence();
        const unsigned old = atomicAdd(&g_bar, 1u);
        const unsigned tgt = (old / GRID_MAIN + 1u) * GRID_MAIN;
        while (*(volatile unsigned*)&g_bar < tgt) { }
        __threadfence();
    }
    __syncthreads();

    // ---- Phase 2: streaming ----
    int gtile = 0, cst = 0, cph = 0;

    if (ctype == 1) {
        // ------------- sentiment: two softmax streams -------------
        const float4 w10 = *(const float4*)(w_ss + lane * 4);
        const float4 w11 = *(const float4*)(w_ss + 128 + lane * 4);
        const float4 w20 = *(const float4*)(w_sa + lane * 4);
        const float4 w21 = *(const float4*)(w_sa + 128 + lane * 4);

        for (int j = 0; j < nit; j++) {
            const int e = tcta + CPT * j;
            const int b = e >> 5, s = e & 31;
            const float* mrow = mask + (size_t)b * T_ + s * ROWS_ITEM;

            float l1 = 0.f, l2 = 0.f;
            float4 p0 = {0,0,0,0}, p1 = {0,0,0,0};
            float4 q0 = {0,0,0,0}, q1 = {0,0,0,0};

            for (int t = 0; t < TPI; t++) {
                mbar_wait(mb_full + cst * 8, cph);
                const float* buf = s_data + cst * TILE_FLOATS;
#pragma unroll
                for (int r = 0; r < TILE_ROWS / NW; r++) {
                    const int row = w * (TILE_ROWS / NW) + r;
                    const float4 r0 = *(const float4*)(buf + row * D_ + lane * 4);
                    const float4 r1 = *(const float4*)(buf + row * D_ + 128 + lane * 4);
                    const float mk = mrow[t * TILE_ROWS + row];
                    float d1 = dot8(r0, w10, r1, w11);
                    float d2 = dot8(r0, w20, r1, w21);
#pragma unroll
                    for (int o = 16; o > 0; o >>= 1) {
                        d1 += __shfl_xor_sync(0xffffffffu, d1, o);
                        d2 += __shfl_xor_sync(0xffffffffu, d2, o);
                    }
                    const float pe1 = __expf(d1) * mk;
                    const float pe2 = __expf(d2) * mk;
                    l1 += pe1;  l2 += pe2;
                    p0.x += pe1*r0.x; p0.y += pe1*r0.y; p0.z += pe1*r0.z; p0.w += pe1*r0.w;
                    p1.x += pe1*r1.x; p1.y += pe1*r1.y; p1.z += pe1*r1.z; p1.w += pe1*r1.w;
                    q0.x += pe2*r0.x; q0.y += pe2*r0.y; q0.z += pe2*r0.z; q0.w += pe2*r0.w;
                    q1.x += pe2*r1.x; q1.y += pe2*r1.y; q1.z += pe2*r1.z; q1.w += pe2*r1.w;
                }
                mbar_arrive(mb_empty + cst * 8);
                if (tid == 0 && gtile + NSTAGE < ntile) {
                    mbar_wait(mb_empty + cst * 8, cph);
                    mbar_expect_tx(mb_full + cst * 8, TILE_BYTES);
                    bulk_g2s(sdata + cst * TILE_BYTES,
                             pbase + (size_t)pt * TILE_FLOATS, TILE_BYTES,
                             mb_full + cst * 8);
                    if (++pt == TPI) {
                        pt = 0; pj++;
                        if (pj < nit) {
                            const int e2 = tcta + CPT * pj;
                            pbase = membase + ((size_t)(e2 >> 5) * T_
                                             + (size_t)(e2 & 31) * ROWS_ITEM) * D_;
                        }
                    }
                }
                gtile++;
                if (++cst == NSTAGE) { cst = 0; cph ^= 1; }
            }

            // flush stream 1
            *(float4*)&s_red[w * D_ + lane * 4]       = p0;
            *(float4*)&s_red[w * D_ + 128 + lane * 4] = p1;
            if (lane == 0) s_lred[w] = l1;
            __syncthreads();
            {
                float v = 0.f, L = 0.f;
#pragma unroll
                for (int ww = 0; ww < NW; ww++) { v += s_red[ww * D_ + tid]; L += s_lred[ww]; }
                g_p1[e][tid] = v;
                if (tid == 0) g_p1[e][256] = L;
            }
            __syncthreads();
            // flush stream 2
            *(float4*)&s_red[w * D_ + lane * 4]       = q0;
            *(float4*)&s_red[w * D_ + 128 + lane * 4] = q1;
            if (lane == 0) s_lred[w] = l2;
            __syncthreads();
            {
                float v = 0.f, L = 0.f;
#pragma unroll
                for (int ww = 0; ww < NW; ww++) { v += s_red[ww * D_ + tid]; L += s_lred[ww]; }
                g_p2[e][tid] = v;
                if (tid == 0) g_p2[e][256] = L;
            }
            __syncthreads();

            // Fused combine: 32nd completer of b merges all partials.
            if (tid == 0) {
                __threadfence();
                const unsigned old = atomicAdd(&g_cnt_s[b], 1u);
                s_doc = ((old & 31u) == 31u);
            }
            __syncthreads();
            if (s_doc) {
                __threadfence();
                float v1 = 0.f, L1 = 0.f, v2 = 0.f, L2 = 0.f;
#pragma unroll 8
                for (int s2 = 0; s2 < S_; s2++) {
                    const int i = b * S_ + s2;
                    v1 += g_p1[i][tid];  L1 += g_p1[i][256];
                    v2 += g_p2[i][tid];  L2 += g_p2[i][256];
                }
                out[b * D_ + tid] = 0.5f * (v1 / L1) + 0.5f * (v2 / L2);
            }
        }
    } else {
        // ------------- aspect: tanh-score softmax -------------
        const float bm = b_mul[0];
        for (int j = 0; j < nit; j++) {
            const int e = tcta + CPT * j;
            const int b = e >> 5;
            const float4 md0 = *(const float4*)(g_mids + b * D_ + lane * 4);
            const float4 md1 = *(const float4*)(g_mids + b * D_ + 128 + lane * 4);

            float l = 0.f;
            float4 a0 = {0,0,0,0}, a1 = {0,0,0,0};

            for (int t = 0; t < TPI; t++) {
                mbar_wait(mb_full + cst * 8, cph);
                const float* buf = s_data + cst * TILE_FLOATS;
#pragma unroll
                for (int r = 0; r < TILE_ROWS / NW; r++) {
                    const int row = w * (TILE_ROWS / NW) + r;
                    const float4 r0 = *(const float4*)(buf + row * D_ + lane * 4);
                    const float4 r1 = *(const float4*)(buf + row * D_ + 128 + lane * 4);
                    float p = dot8(r0, md0, r1, md1);
                    p = warp_sum(p);
                    const float pe = __expf(tanhf(p + bm));
                    l += pe;
                    a0.x += pe*r0.x; a0.y += pe*r0.y; a0.z += pe*r0.z; a0.w += pe*r0.w;
                    a1.x += pe*r1.x; a1.y += pe*r1.y; a1.z += pe*r1.z; a1.w += pe*r1.w;
                }
                mbar_arrive(mb_empty + cst * 8);
                if (tid == 0 && gtile + NSTAGE < ntile) {
                    mbar_wait(mb_empty + cst * 8, cph);
                    mbar_expect_tx(mb_full + cst * 8, TILE_BYTES);
                    bulk_g2s(sdata + cst * TILE_BYTES,
                             pbase + (size_t)pt * TILE_FLOATS, TILE_BYTES,
                             mb_full + cst * 8);
                    if (++pt == TPI) {
                        pt = 0; pj++;
                        if (pj < nit) {
                            const int e2 = tcta + CPT * pj;
                            pbase = membase + ((size_t)(e2 >> 5) * T_
                                             + (size_t)(e2 & 31) * ROWS_ITEM) * D_;
                        }
                    }
                }
                gtile++;
                if (++cst == NSTAGE) { cst = 0; cph ^= 1; }
            }

            *(float4*)&s_red[w * D_ + lane * 4]       = a0;
            *(float4*)&s_red[w * D_ + 128 + lane * 4] = a1;
            if (lane == 0) s_lred[w] = l;
            __syncthreads();
            {
                float v = 0.f, L = 0.f;
#pragma unroll
                for (int ww = 0; ww < NW; ww++) { v += s_red[ww * D_ + tid]; L += s_lred[ww]; }
                g_pa[e][tid] = v;
                if (tid == 0) g_pa[e][256] = L;
            }
            __syncthreads();

            // Fused combine for aspect_out.
            if (tid == 0) {
                __threadfence();
                const unsigned old = atomicAdd(&g_cnt_a[b], 1u);
                s_doc = ((old & 31u) == 31u);
            }
            __syncthreads();
            if (s_doc) {
                __threadfence();
                float va = 0.f, La = 0.f;
#pragma unroll 8
                for (int s2 = 0; s2 < S_; s2++) {
                    const int i = b * S_ + s2;
                    va += g_pa[i][tid];  La += g_pa[i][256];
                }
                out[B_ * D_ + b * D_ + tid] = aspect[b * D_ + tid] + va / La;
            }
        }
    }
}

// ---------------------------------------------------------------------------
// kernel_launch. Inputs (metadata order):
//  0 sentiment  1 aspect  2 sentiment_memory  3 aspect_memory  4 mask
//  5 W_mul  6 b_mul  7 w_ss  8 b_ss  9 w_sa  10 b_sa
// Query-side additive terms (w[D:], biases) cancel in the softmax -> unused.
// Output: sentiment_out [0, B*D), aspect_out [B*D, 2*B*D).
// ---------------------------------------------------------------------------
extern "C" void kernel_launch(void* const* d_in, const int* in_sizes, int n_in,
                              void* d_out, int out_size)
{
    const float* aspect           = (const float*)d_in[1];
    const float* sentiment_memory = (const float*)d_in[2];
    const float* aspect_memory    = (const float*)d_in[3];
    const float* mask             = (const float*)d_in[4];
    const float* W_mul            = (const float*)d_in[5];
    const float* b_mul            = (const float*)d_in[6];
    const float* w_ss             = (const float*)d_in[7];
    const float* w_sa             = (const float*)d_in[9];
    float* out = (float*)d_out;

    cudaFuncSetAttribute(k_main, cudaFuncAttributeMaxDynamicSharedMemorySize,
                         SMEM_TOTAL);
    k_main<<<GRID_MAIN, NTHREADS, SMEM_TOTAL>>>(
        aspect, sentiment_memory, aspect_memory, mask, W_mul, b_mul,
        w_ss, w_sa, out);
}

// round 10
// speedup vs baseline: 1.1441x; 1.1441x over previous
#include <cuda_runtime.h>
#include <cstdint>

// Problem constants: B=128, T=2048, D=256, LAMDA=0.5
#define B_ 128
#define T_ 2048
#define D_ 256
#define S_ 32                          // T-splits (chunks) per (b, tensor)
#define ROWS_ITEM (T_ / S_)            // 64 rows per chunk
#define NW 8
#define NTHREADS 256
#define GRID_MAIN 592                  // 148 SMs x 4 CTAs
#define CPT (GRID_MAIN / 2)            // 296 CTAs per tensor type
#define NIT (B_ * S_)                  // 4096 chunks per tensor
#define NDOTS (B_ * D_)                // 32768 mids row-dots
#define ROWS_W (ROWS_ITEM / NW)        // 8 rows per warp per chunk

// Globals (zero-initialized; counters monotonic + modular -> graph-replay safe).
__device__ float g_mids[B_ * D_];
__device__ float g_pa[NIT][258];   // aspect partials (acc[256], L at [256])
__device__ float g_p1[NIT][258];   // sentiment-sentiment partials
__device__ float g_p2[NIT][258];   // sentiment-aspect partials
__device__ unsigned g_bar;         // aspect-side barrier counter (+CPT per launch)
__device__ unsigned g_cnt_s[B_];   // sentiment completion counters (+32/launch)
__device__ unsigned g_cnt_a[B_];   // aspect completion counters    (+32/launch)

__device__ __forceinline__ float warp_sum(float v) {
#pragma unroll
    for (int o = 16; o > 0; o >>= 1) v += __shfl_xor_sync(0xffffffffu, v, o);
    return v;
}
__device__ __forceinline__ float dot8(float4 a, float4 b, float4 c, float4 d) {
    return a.x*b.x + a.y*b.y + a.z*b.z + a.w*b.w
         + c.x*d.x + c.y*d.y + c.z*d.z + c.w*d.w;
}
#define FMA4(acc, s, r) \
    acc.x += (s)*(r).x; acc.y += (s)*(r).y; acc.z += (s)*(r).z; acc.w += (s)*(r).w;

// ---------------------------------------------------------------------------
// k_main: ONE kernel, grid = 592 (4 CTAs/SM, 32 warps/SM). Pure-LDG stream —
// no smem data staging (zero reuse; occupancy+MLP covers DRAM latency).
// Even CTAs: compute mids = W_mul @ aspect cooperatively, barrier among
//            aspect CTAs only, then stream aspect_memory (tanh softmax).
// Odd CTAs:  stream sentiment_memory immediately (two softmax streams).
// The 32nd CTA to finish a b's chunks performs that b's final combine.
// No online max needed: aspect scores = tanh in [-1,1]; sentiment scores are
// O(1) -> plain exp() is safe and equals the reference's shifted softmax.
// Query-side additive terms are constant over t and cancel in the softmax.
// ---------------------------------------------------------------------------
__global__ void __launch_bounds__(NTHREADS, 4) k_main(
    const float* __restrict__ aspect,            // [B,D]
    const float* __restrict__ sentiment_memory,  // [B,T,D]
    const float* __restrict__ aspect_memory,     // [B,T,D]
    const float* __restrict__ mask,              // [B,T]
    const float* __restrict__ W_mul,             // [D,D]
    const float* __restrict__ b_mul,             // [1]
    const float* __restrict__ w_ss,              // [2D] (only [:D] matters)
    const float* __restrict__ w_sa,              // [2D]
    float* __restrict__ out)                     // [2*B*D]
{
    __shared__ __align__(16) float s_red[NW * D_];
    __shared__ float s_lred[NW];
    __shared__ int s_doc;

    const int cta   = blockIdx.x;
    const int ctype = cta & 1;          // 0 = aspect, 1 = sentiment
    const int tcta  = cta >> 1;
    const int tid   = threadIdx.x;
    const int w     = tid >> 5, lane = tid & 31;

    const int nit = (NIT - tcta + CPT - 1) / CPT;
    const float* membase = ctype ? sentiment_memory : aspect_memory;

    if (ctype == 0) {
        // ---- mids GEMV by aspect CTAs only (sentiment half streams now) ----
        const int gid = tcta * NW + w;
        for (int idx = gid; idx < NDOTS; idx += CPT * NW) {
            const int b   = idx >> 8;
            const int row = idx & (D_ - 1);
            const float4* Wr = (const float4*)(W_mul + (size_t)row * D_);
            const float4* Ar = (const float4*)(aspect + (size_t)b * D_);
            float p = dot8(Wr[lane], Ar[lane], Wr[32 + lane], Ar[32 + lane]);
            p = warp_sum(p);
            if (lane == 0) g_mids[b * D_ + row] = p;
        }
        __syncthreads();
        // Replay-safe barrier among the CPT aspect CTAs (monotonic counter).
        if (tid == 0) {
            __threadfence();
            const unsigned old = atomicAdd(&g_bar, 1u);
            const unsigned tgt = (old / CPT + 1u) * CPT;
            while (*(volatile unsigned*)&g_bar < tgt) { }
            __threadfence();
        }
        __syncthreads();
    }

    if (ctype == 1) {
        // ------------- sentiment: two softmax streams -------------
        const float4 w10 = *(const float4*)(w_ss + lane * 4);
        const float4 w11 = *(const float4*)(w_ss + 128 + lane * 4);
        const float4 w20 = *(const float4*)(w_sa + lane * 4);
        const float4 w21 = *(const float4*)(w_sa + 128 + lane * 4);

        for (int j = 0; j < nit; j++) {
            const int e = tcta + CPT * j;
            const int b = e >> 5, s = e & 31;
            const float4* m4  = (const float4*)(sentiment_memory
                              + ((size_t)b * T_ + (size_t)s * ROWS_ITEM) * D_);
            const float* mrow = mask + (size_t)b * T_ + s * ROWS_ITEM;

            float l1 = 0.f, l2 = 0.f;
            float4 p0 = {0,0,0,0}, p1 = {0,0,0,0};
            float4 q0 = {0,0,0,0}, q1 = {0,0,0,0};

#pragma unroll
            for (int rr = 0; rr < ROWS_W; rr += 2) {
                const int row = w * ROWS_W + rr;
                // Front-batched loads: 4 LDG.128 + 2 scalar in flight.
                const float4 r0a = m4[(size_t)row * 64 + lane];
                const float4 r1a = m4[(size_t)row * 64 + 32 + lane];
                const float4 r0b = m4[(size_t)(row + 1) * 64 + lane];
                const float4 r1b = m4[(size_t)(row + 1) * 64 + 32 + lane];
                const float mka = mrow[row];
                const float mkb = mrow[row + 1];

                float d1a = dot8(r0a, w10, r1a, w11);
                float d2a = dot8(r0a, w20, r1a, w21);
                float d1b = dot8(r0b, w10, r1b, w11);
                float d2b = dot8(r0b, w20, r1b, w21);
#pragma unroll
                for (int o = 16; o > 0; o >>= 1) {
                    d1a += __shfl_xor_sync(0xffffffffu, d1a, o);
                    d2a += __shfl_xor_sync(0xffffffffu, d2a, o);
                    d1b += __shfl_xor_sync(0xffffffffu, d1b, o);
                    d2b += __shfl_xor_sync(0xffffffffu, d2b, o);
                }
                const float pe1a = __expf(d1a) * mka;
                const float pe2a = __expf(d2a) * mka;
                const float pe1b = __expf(d1b) * mkb;
                const float pe2b = __expf(d2b) * mkb;
                l1 += pe1a + pe1b;
                l2 += pe2a + pe2b;
                FMA4(p0, pe1a, r0a)  FMA4(p1, pe1a, r1a)
                FMA4(q0, pe2a, r0a)  FMA4(q1, pe2a, r1a)
                FMA4(p0, pe1b, r0b)  FMA4(p1, pe1b, r1b)
                FMA4(q0, pe2b, r0b)  FMA4(q1, pe2b, r1b)
            }

            // flush stream 1
            *(float4*)&s_red[w * D_ + lane * 4]       = p0;
            *(float4*)&s_red[w * D_ + 128 + lane * 4] = p1;
            if (lane == 0) s_lred[w] = l1;
            __syncthreads();
            {
                float v = 0.f, L = 0.f;
#pragma unroll
                for (int ww = 0; ww < NW; ww++) { v += s_red[ww * D_ + tid]; L += s_lred[ww]; }
                g_p1[e][tid] = v;
                if (tid == 0) g_p1[e][256] = L;
            }
            __syncthreads();
            // flush stream 2
            *(float4*)&s_red[w * D_ + lane * 4]       = q0;
            *(float4*)&s_red[w * D_ + 128 + lane * 4] = q1;
            if (lane == 0) s_lred[w] = l2;
            __syncthreads();
            {
                float v = 0.f, L = 0.f;
#pragma unroll
                for (int ww = 0; ww < NW; ww++) { v += s_red[ww * D_ + tid]; L += s_lred[ww]; }
                g_p2[e][tid] = v;
                if (tid == 0) g_p2[e][256] = L;
            }
            __syncthreads();

            // Fused combine: 32nd completer of b merges all its partials.
            if (tid == 0) {
                __threadfence();
                const unsigned old = atomicAdd(&g_cnt_s[b], 1u);
                s_doc = ((old & 31u) == 31u);
            }
            __syncthreads();
            if (s_doc) {
                __threadfence();
                float v1 = 0.f, L1 = 0.f, v2 = 0.f, L2 = 0.f;
#pragma unroll 8
                for (int s2 = 0; s2 < S_; s2++) {
                    const int i = b * S_ + s2;
                    v1 += g_p1[i][tid];  L1 += g_p1[i][256];
                    v2 += g_p2[i][tid];  L2 += g_p2[i][256];
                }
                out[b * D_ + tid] = 0.5f * (v1 / L1) + 0.5f * (v2 / L2);
            }
            __syncthreads();
        }
    } else {
        // ------------- aspect: tanh-score softmax -------------
        const float bm = b_mul[0];
        for (int j = 0; j < nit; j++) {
            const int e = tcta + CPT * j;
            const int b = e >> 5, s = e & 31;
            const float4* m4 = (const float4*)(aspect_memory
                             + ((size_t)b * T_ + (size_t)s * ROWS_ITEM) * D_);
            const float4 md0 = *(const float4*)(g_mids + b * D_ + lane * 4);
            const float4 md1 = *(const float4*)(g_mids + b * D_ + 128 + lane * 4);

            float l = 0.f;
            float4 a0 = {0,0,0,0}, a1 = {0,0,0,0};

#pragma unroll
            for (int rr = 0; rr < ROWS_W; rr += 2) {
                const int row = w * ROWS_W + rr;
                const float4 r0a = m4[(size_t)row * 64 + lane];
                const float4 r1a = m4[(size_t)row * 64 + 32 + lane];
                const float4 r0b = m4[(size_t)(row + 1) * 64 + lane];
                const float4 r1b = m4[(size_t)(row + 1) * 64 + 32 + lane];

                float pa = dot8(r0a, md0, r1a, md1);
                float pb = dot8(r0b, md0, r1b, md1);
#pragma unroll
                for (int o = 16; o > 0; o >>= 1) {
                    pa += __shfl_xor_sync(0xffffffffu, pa, o);
                    pb += __shfl_xor_sync(0xffffffffu, pb, o);
                }
                const float pea = __expf(tanhf(pa + bm));
                const float peb = __expf(tanhf(pb + bm));
                l += pea + peb;
                FMA4(a0, pea, r0a)  FMA4(a1, pea, r1a)
                FMA4(a0, peb, r0b)  FMA4(a1, peb, r1b)
            }

            *(float4*)&s_red[w * D_ + lane * 4]       = a0;
            *(float4*)&s_red[w * D_ + 128 + lane * 4] = a1;
            if (lane == 0) s_lred[w] = l;
            __syncthreads();
            {
                float v = 0.f, L = 0.f;
#pragma unroll
                for (int ww = 0; ww < NW; ww++) { v += s_red[ww * D_ + tid]; L += s_lred[ww]; }
                g_pa[e][tid] = v;
                if (tid == 0) g_pa[e][256] = L;
            }
            __syncthreads();

            if (tid == 0) {
                __threadfence();
                const unsigned old = atomicAdd(&g_cnt_a[b], 1u);
                s_doc = ((old & 31u) == 31u);
            }
            __syncthreads();
            if (s_doc) {
                __threadfence();
                float va = 0.f, La = 0.f;
#pragma unroll 8
                for (int s2 = 0; s2 < S_; s2++) {
                    const int i = b * S_ + s2;
                    va += g_pa[i][tid];  La += g_pa[i][256];
                }
                out[B_ * D_ + b * D_ + tid] = aspect[b * D_ + tid] + va / La;
            }
            __syncthreads();
        }
    }
}

// ---------------------------------------------------------------------------
// kernel_launch. Inputs (metadata order):
//  0 sentiment  1 aspect  2 sentiment_memory  3 aspect_memory  4 mask
//  5 W_mul  6 b_mul  7 w_ss  8 b_ss  9 w_sa  10 b_sa
// Query-side additive terms (w[D:], biases) cancel in the softmax -> unused.
// Output: sentiment_out [0, B*D), aspect_out [B*D, 2*B*D).
// ---------------------------------------------------------------------------
extern "C" void kernel_launch(void* const* d_in, const int* in_sizes, int n_in,
                              void* d_out, int out_size)
{
    const float* aspect           = (const float*)d_in[1];
    const float* sentiment_memory = (const float*)d_in[2];
    const float* aspect_memory    = (const float*)d_in[3];
    const float* mask             = (const float*)d_in[4];
    const float* W_mul            = (const float*)d_in[5];
    const float* b_mul            = (const float*)d_in[6];
    const float* w_ss             = (const float*)d_in[7];
    const float* w_sa             = (const float*)d_in[9];
    float* out = (float*)d_out;

    k_main<<<GRID_MAIN, NTHREADS>>>(
        aspect, sentiment_memory, aspect_memory, mask, W_mul, b_mul,
        w_ss, w_sa, out);
}